// round 16
// baseline (speedup 1.0000x reference)
#include <cuda_runtime.h>
#include <cuda_fp16.h>
#include <math.h>
#include <stdint.h>

// InfoNCE loss: single-pass fp16 HMMA GEMM (f32 acc) + fused online LSE.
// Exact self-masking via RARE-BRANCH guard: only the 0.8% of warp-instances
// whose rows contain the self element run the mask loop; everyone else pays
// ~6 instrs. Warp-private double-buffered A; one barrier per CTA; occ 2.
// Inputs: out f32 [512,128], keys f32 [512,512,128], self_index i32 [512]
// Output: scalar f32 loss.

#define BQ      512
#define DD      128
#define KPB     512
#define TILEN   128
#define NTILES  ((BQ * KPB) / TILEN)  // 2048
#define INV_T   14.285714285714285f
#define NEG_BIG -1.0e30f

// ---------------- global scratch (allocation-free rule) ----------------
__device__ __align__(256) __half g_qh[BQ * DD];          // queries * INV_T, fp16
__device__ float g_pm[BQ * NTILES], g_ps[BQ * NTILES];
__device__ float g_loss[BQ];
__device__ unsigned int g_done;                          // completion counter (self-resets)

// ---------------- PTX helpers ----------------
__device__ __forceinline__ uint32_t smem_u32(const void* p) {
    uint32_t a;
    asm("{ .reg .u64 t; cvta.to.shared.u64 t, %1; cvt.u32.u64 %0, t; }" : "=r"(a) : "l"(p));
    return a;
}
__device__ __forceinline__ void ldmx4(uint32_t* r, uint32_t addr) {
    asm volatile("ldmatrix.sync.aligned.m8n8.x4.shared.b16 {%0,%1,%2,%3}, [%4];"
                 : "=r"(r[0]), "=r"(r[1]), "=r"(r[2]), "=r"(r[3]) : "r"(addr));
}
__device__ __forceinline__ void hmma16816(float* c, const uint32_t* a, const uint32_t* b) {
    asm volatile("mma.sync.aligned.m16n8k16.row.col.f32.f16.f16.f32 "
                 "{%0,%1,%2,%3},{%4,%5,%6,%7},{%8,%9},{%0,%1,%2,%3};"
                 : "+f"(c[0]), "+f"(c[1]), "+f"(c[2]), "+f"(c[3])
                 : "r"(a[0]), "r"(a[1]), "r"(a[2]), "r"(a[3]), "r"(b[0]), "r"(b[1]));
}
#define CPASYNC16(s, g) asm volatile("cp.async.cg.shared.global [%0], [%1], 16;" :: "r"(s), "l"(g))
#define CP_COMMIT()     asm volatile("cp.async.commit_group;" ::: "memory")
#define CP_WAIT0()      asm volatile("cp.async.wait_group 0;" ::: "memory")
#define CP_WAIT1()      asm volatile("cp.async.wait_group 1;" ::: "memory")

// ---------------------------------------------------------------------------
// Kernel 0: queries f32 -> fp16 * INV_T (folds temperature into A once).
// ---------------------------------------------------------------------------
__global__ __launch_bounds__(256)
void qconv(const float* __restrict__ Q)
{
    const int t = blockIdx.x * 256 + threadIdx.x;      // 4096 threads
    #pragma unroll
    for (int i = 0; i < 4; i++) {
        int f = t + i * 4096;                          // float4 index 0..16383
        float4 v = ((const float4*)Q)[f];
        __half2 h0 = __floats2half2_rn(v.x * INV_T, v.y * INV_T);
        __half2 h1 = __floats2half2_rn(v.z * INV_T, v.w * INV_T);
        ((uint2*)g_qh)[f] = make_uint2(*(uint32_t*)&h0, *(uint32_t*)&h1);
    }
}

// ---------------- SMEM layout ----------------
// B: 128 rows x 128 fp16 (stride 272 -> ldmatrix conflict-free).
// A: 8 warps x 2 buffers x 16 rows x 272 B (warp-private double buffer).
#define TSTRIDE 272u
#define OFF_B   0u
#define OFF_A   34816u
#define ABUF    4352u                       // 16*272 bytes, one warp slice
#define SMEM_SZ 104448u                     // 34816 + 8*2*4352

// warp loads ITS 16 rows of m-block mb into slice buffer (8 chunks/lane)
__device__ __forceinline__ void load_a_warp(uint32_t s_slice, int mb, int wid, int lane)
{
    const char* gbase = (const char*)g_qh + (size_t)(mb * 128 + wid * 16) * 256;
    #pragma unroll
    for (int i = 0; i < 8; i++) {
        int idx = lane + i * 32;            // 0..255 chunks (16 rows x 16)
        int r   = idx >> 4;
        int c   = idx & 15;
        CPASYNC16(s_slice + r * TSTRIDE + c * 16, gbase + (size_t)r * 256 + c * 16);
    }
}

// ---------------------------------------------------------------------------
// Kernel 1: one CTA per 128-key tile; B converted f32->f16 in-CTA; each warp
// pipelines its private A slices across the 4 m-blocks. One block barrier.
// Self-mask applied EXACTLY but behind a rarely-taken guard.
// ---------------------------------------------------------------------------
__global__ __launch_bounds__(256, 2)
void gemm_lse_hmma(const float* __restrict__ Km, const int* __restrict__ sidx)
{
    extern __shared__ char smem[];
    const uint32_t sb = smem_u32(smem);
    const int tid  = threadIdx.x;
    const int wid  = tid >> 5;
    const int lane = tid & 31;
    const int tile = blockIdx.x;
    const int colBase = tile * TILEN;
    const uint32_t aw = sb + OFF_A + wid * (2u * ABUF);  // this warp's 2 buffers

    // issue A(0) into buffer 0, then convert B tile f32 -> f16 smem
    load_a_warp(aw, 0, wid, lane);
    CP_COMMIT();
    #pragma unroll
    for (int i = 0; i < 16; i++) {
        int f  = tid + i * 256;             // float4 index 0..4095 (32 per row)
        int r  = f >> 5;
        int c4 = f & 31;
        float4 v = *(const float4*)(Km + (size_t)(colBase + r) * DD + c4 * 4);
        __half2 h0 = __floats2half2_rn(v.x, v.y);
        __half2 h1 = __floats2half2_rn(v.z, v.w);
        *(uint2*)(smem + OFF_B + r * TSTRIDE + c4 * 8)
            = make_uint2(*(uint32_t*)&h0, *(uint32_t*)&h1);
    }
    __syncthreads();                        // the ONLY block barrier (B ready)

    const uint32_t brow = sb + OFF_B + (lane & 15) * TSTRIDE + (lane >> 4) * 16;

    #pragma unroll 1
    for (int mb = 0; mb < 4; mb++) {
        // issue next slice into the other buffer, then complete current group
        if (mb < 3) {
            load_a_warp(aw + ((mb + 1) & 1) * ABUF, mb + 1, wid, lane);
            CP_COMMIT();
            CP_WAIT1();                     // A(mb) done, A(mb+1) in flight
        } else {
            CP_WAIT0();                     // last slice
        }
        __syncwarp();

        float acc[16][4];                   // ni 0..15 (n8 tiles), 4 regs each
        #pragma unroll
        for (int ni = 0; ni < 16; ni++)
            #pragma unroll
            for (int r = 0; r < 4; r++) acc[ni][r] = 0.0f;

        const uint32_t arow = aw + (mb & 1) * ABUF
                            + (lane & 15) * TSTRIDE + (lane >> 4) * 16;
        #pragma unroll
        for (int kk = 0; kk < 8; kk++) {                // 8 k-steps of 16 halves
            uint32_t a[4];
            ldmx4(a, arow + kk * 32);
            #pragma unroll
            for (int t = 0; t < 8; t++) {               // 16 key rows per t
                uint32_t bq[4];
                ldmx4(bq, brow + kk * 32 + t * 16 * TSTRIDE);
                uint32_t b0[2] = {bq[0], bq[2]};        // n8 tile 2t
                uint32_t b1[2] = {bq[1], bq[3]};        // n8 tile 2t+1
                hmma16816(acc[2 * t],     a, b0);
                hmma16816(acc[2 * t + 1], a, b1);
            }
        }

        // ---- epilogue: fully in-warp; EXACT self-mask behind rare guard ----
        {
            const int r0l = wid * 16 + (lane >> 2);
            const int q0 = mb * 128 + r0l, q1 = q0 + 8;
            const int msk0 = q0 * KPB + __ldg(&sidx[q0]) - colBase;
            const int msk1 = q1 * KPB + __ldg(&sidx[q1]) - colBase;

            // taken by ~0.8% of warp-instances: overwrite the ONE self logit
            if ((unsigned)msk0 < 128u) {
                #pragma unroll
                for (int ni = 0; ni < 16; ni++) {
                    const int c = ni * 8 + 2 * (lane & 3);
                    if (c     == msk0) acc[ni][0] = NEG_BIG;
                    if (c + 1 == msk0) acc[ni][1] = NEG_BIG;
                }
            }
            if ((unsigned)msk1 < 128u) {
                #pragma unroll
                for (int ni = 0; ni < 16; ni++) {
                    const int c = ni * 8 + 2 * (lane & 3);
                    if (c     == msk1) acc[ni][2] = NEG_BIG;
                    if (c + 1 == msk1) acc[ni][3] = NEG_BIG;
                }
            }

            float m0 = -3.0e38f, m1 = -3.0e38f;
            #pragma unroll
            for (int ni = 0; ni < 16; ni++) {
                m0 = fmaxf(m0, fmaxf(acc[ni][0], acc[ni][1]));
                m1 = fmaxf(m1, fmaxf(acc[ni][2], acc[ni][3]));
            }
            #pragma unroll
            for (int o = 1; o < 4; o <<= 1) {           // row max over the quad
                m0 = fmaxf(m0, __shfl_xor_sync(0xFFFFFFFFu, m0, o));
                m1 = fmaxf(m1, __shfl_xor_sync(0xFFFFFFFFu, m1, o));
            }
            float s0 = 0.0f, s1 = 0.0f;
            #pragma unroll
            for (int ni = 0; ni < 16; ni++) {
                s0 += __expf(acc[ni][0] - m0) + __expf(acc[ni][1] - m0);
                s1 += __expf(acc[ni][2] - m1) + __expf(acc[ni][3] - m1);
            }
            #pragma unroll
            for (int o = 1; o < 4; o <<= 1) {           // row sum over the quad
                s0 += __shfl_xor_sync(0xFFFFFFFFu, s0, o);
                s1 += __shfl_xor_sync(0xFFFFFFFFu, s1, o);
            }
            if ((lane & 3) == 0) {
                g_pm[q0 * NTILES + tile] = m0; g_ps[q0 * NTILES + tile] = s0;
                g_pm[q1 * NTILES + tile] = m1; g_ps[q1 * NTILES + tile] = s1;
            }
        }
    }
}

// ---------------------------------------------------------------------------
// Kernel 2 (fused): per query, reduce 2048 (m,s) partials -> total LSE;
// own-bag tiles (4b..4b+3) + 261632 exp(0) -> positive LSE; per-query loss.
// Last block sums g_loss in fixed order -> mean; counter self-resets.
// ---------------------------------------------------------------------------
__global__ void reduce_all(float* __restrict__ out)
{
    __shared__ float sm[256], ss[256];
    __shared__ unsigned int is_last;
    const int b = blockIdx.x, tid = threadIdx.x;

    float m = -3.0e38f, s = 0.0f;
    for (int t = tid; t < NTILES; t += 256) {
        float mo = g_pm[b * NTILES + t], so = g_ps[b * NTILES + t];
        float M = fmaxf(m, mo);
        s = s * __expf(m - M) + so * __expf(mo - M);
        m = M;
    }
    sm[tid] = m; ss[tid] = s;
    __syncthreads();
    for (int st = 128; st > 0; st >>= 1) {
        if (tid < st) {
            float m1 = sm[tid], m2 = sm[tid + st];
            float s1 = ss[tid], s2 = ss[tid + st];
            float M = fmaxf(m1, m2);
            sm[tid] = M;
            ss[tid] = s1 * __expf(m1 - M) + s2 * __expf(m2 - M);
        }
        __syncthreads();
    }
    if (tid == 0) {
        float lse_tot = sm[0] + logf(ss[0]);

        float mp = -3.0e38f, sp = 0.0f;
        #pragma unroll
        for (int p = 0; p < 4; p++) {                  // positive tiles = 4b..4b+3
            float mo = g_pm[b * NTILES + 4 * b + p];
            float so = g_ps[b * NTILES + 4 * b + p];
            float M = fmaxf(mp, mo);
            sp = sp * __expf(mp - M) + so * __expf(mo - M);
            mp = M;
        }
        // s_*labels keeps negatives as exp(0)=1: B*K - K = 261632 of them
        float Mp = fmaxf(mp, 0.0f);
        float Sp = sp * __expf(mp - Mp) + 261632.0f * __expf(-Mp);
        float lse_p = Mp + logf(Sp);

        g_loss[b] = -lse_p + logf(511.0f) + lse_tot;      // num_p = 512 -> 511

        __threadfence();
        is_last = (atomicAdd(&g_done, 1u) == BQ - 1) ? 1u : 0u;
    }
    __syncthreads();
    if (is_last) {                           // final mean, fixed order (deterministic)
        __threadfence();
        sm[tid] = g_loss[tid] + g_loss[tid + 256];
        __syncthreads();
        for (int st = 128; st > 0; st >>= 1) {
            if (tid < st) sm[tid] += sm[tid + st];
            __syncthreads();
        }
        if (tid == 0) {
            out[0] = sm[0] * (1.0f / 512.0f);
            g_done = 0;                      // reset for next graph replay
        }
    }
}

// ---------------------------------------------------------------------------
extern "C" void kernel_launch(void* const* d_in, const int* in_sizes, int n_in,
                              void* d_out, int out_size)
{
    const float* Q    = (const float*)d_in[0];   // [512,128]
    const float* Km   = (const float*)d_in[1];   // [512,512,128]
    const int*   sidx = (const int*)  d_in[2];   // [512]

    cudaFuncSetAttribute(gemm_lse_hmma, cudaFuncAttributeMaxDynamicSharedMemorySize, SMEM_SZ);

    qconv<<<16, 256>>>(Q);
    gemm_lse_hmma<<<NTILES, 256, SMEM_SZ>>>(Km, sidx);
    reduce_all<<<BQ, 256>>>((float*)d_out);
}

// round 17
// speedup vs baseline: 1.0241x; 1.0241x over previous
#include <cuda_runtime.h>
#include <cuda_fp16.h>
#include <math.h>
#include <stdint.h>

// InfoNCE loss: single-pass fp16 HMMA GEMM (f32 acc) + fused online LSE.
// BASE-2 logits: queries pre-scaled by INV_T*log2(e) so every exponential is
// a bare MUFU.EX2 (exp2f), no FFMA. Exact self-mask behind a rare branch.
// Warp-private double-buffered A; one barrier per CTA; occ 2; fused reduce.
// Inputs: out f32 [512,128], keys f32 [512,512,128], self_index i32 [512]
// Output: scalar f32 loss.

#define BQ      512
#define DD      128
#define KPB     512
#define TILEN   128
#define NTILES  ((BQ * KPB) / TILEN)  // 2048
#define INV_T   14.285714285714285f
#define LOG2E   1.4426950408889634f
#define PRESCALE (INV_T * LOG2E)      // 20.60992915555662
#define LN2     0.6931471805599453f
#define NEG_BIG -1.0e30f

// ---------------- global scratch (allocation-free rule) ----------------
__device__ __align__(256) __half g_qh[BQ * DD];          // queries * PRESCALE, fp16
__device__ float g_pm[BQ * NTILES], g_ps[BQ * NTILES];   // base-2 (max, sumexp2)
__device__ float g_loss[BQ];
__device__ unsigned int g_done;                          // completion counter (self-resets)

// ---------------- PTX helpers ----------------
__device__ __forceinline__ uint32_t smem_u32(const void* p) {
    uint32_t a;
    asm("{ .reg .u64 t; cvta.to.shared.u64 t, %1; cvt.u32.u64 %0, t; }" : "=r"(a) : "l"(p));
    return a;
}
__device__ __forceinline__ void ldmx4(uint32_t* r, uint32_t addr) {
    asm volatile("ldmatrix.sync.aligned.m8n8.x4.shared.b16 {%0,%1,%2,%3}, [%4];"
                 : "=r"(r[0]), "=r"(r[1]), "=r"(r[2]), "=r"(r[3]) : "r"(addr));
}
__device__ __forceinline__ void hmma16816(float* c, const uint32_t* a, const uint32_t* b) {
    asm volatile("mma.sync.aligned.m16n8k16.row.col.f32.f16.f16.f32 "
                 "{%0,%1,%2,%3},{%4,%5,%6,%7},{%8,%9},{%0,%1,%2,%3};"
                 : "+f"(c[0]), "+f"(c[1]), "+f"(c[2]), "+f"(c[3])
                 : "r"(a[0]), "r"(a[1]), "r"(a[2]), "r"(a[3]), "r"(b[0]), "r"(b[1]));
}
#define CPASYNC16(s, g) asm volatile("cp.async.cg.shared.global [%0], [%1], 16;" :: "r"(s), "l"(g))
#define CP_COMMIT()     asm volatile("cp.async.commit_group;" ::: "memory")
#define CP_WAIT0()      asm volatile("cp.async.wait_group 0;" ::: "memory")
#define CP_WAIT1()      asm volatile("cp.async.wait_group 1;" ::: "memory")

// ---------------------------------------------------------------------------
// Kernel 0: queries f32 -> fp16 * (INV_T*log2e): logits come out in base 2.
// ---------------------------------------------------------------------------
__global__ __launch_bounds__(256)
void qconv(const float* __restrict__ Q)
{
    const int t = blockIdx.x * 256 + threadIdx.x;      // 4096 threads
    #pragma unroll
    for (int i = 0; i < 4; i++) {
        int f = t + i * 4096;                          // float4 index 0..16383
        float4 v = ((const float4*)Q)[f];
        __half2 h0 = __floats2half2_rn(v.x * PRESCALE, v.y * PRESCALE);
        __half2 h1 = __floats2half2_rn(v.z * PRESCALE, v.w * PRESCALE);
        ((uint2*)g_qh)[f] = make_uint2(*(uint32_t*)&h0, *(uint32_t*)&h1);
    }
}

// ---------------- SMEM layout ----------------
// B: 128 rows x 128 fp16 (stride 272 -> ldmatrix conflict-free).
// A: 8 warps x 2 buffers x 16 rows x 272 B (warp-private double buffer).
#define TSTRIDE 272u
#define OFF_B   0u
#define OFF_A   34816u
#define ABUF    4352u                       // 16*272 bytes, one warp slice
#define SMEM_SZ 104448u                     // 34816 + 8*2*4352

// warp loads ITS 16 rows of m-block mb into slice buffer (8 chunks/lane)
__device__ __forceinline__ void load_a_warp(uint32_t s_slice, int mb, int wid, int lane)
{
    const char* gbase = (const char*)g_qh + (size_t)(mb * 128 + wid * 16) * 256;
    #pragma unroll
    for (int i = 0; i < 8; i++) {
        int idx = lane + i * 32;            // 0..255 chunks (16 rows x 16)
        int r   = idx >> 4;
        int c   = idx & 15;
        CPASYNC16(s_slice + r * TSTRIDE + c * 16, gbase + (size_t)r * 256 + c * 16);
    }
}

// ---------------------------------------------------------------------------
// Kernel 1: one CTA per 128-key tile; B converted f32->f16 in-CTA; each warp
// pipelines its private A slices across the 4 m-blocks. One block barrier.
// Base-2 epilogue (exp2f = bare EX2); exact self-mask behind rare guard.
// ---------------------------------------------------------------------------
__global__ __launch_bounds__(256, 2)
void gemm_lse_hmma(const float* __restrict__ Km, const int* __restrict__ sidx)
{
    extern __shared__ char smem[];
    const uint32_t sb = smem_u32(smem);
    const int tid  = threadIdx.x;
    const int wid  = tid >> 5;
    const int lane = tid & 31;
    const int tile = blockIdx.x;
    const int colBase = tile * TILEN;
    const uint32_t aw = sb + OFF_A + wid * (2u * ABUF);  // this warp's 2 buffers

    // issue A(0) into buffer 0, then convert B tile f32 -> f16 smem
    load_a_warp(aw, 0, wid, lane);
    CP_COMMIT();
    #pragma unroll
    for (int i = 0; i < 16; i++) {
        int f  = tid + i * 256;             // float4 index 0..4095 (32 per row)
        int r  = f >> 5;
        int c4 = f & 31;
        float4 v = *(const float4*)(Km + (size_t)(colBase + r) * DD + c4 * 4);
        __half2 h0 = __floats2half2_rn(v.x, v.y);
        __half2 h1 = __floats2half2_rn(v.z, v.w);
        *(uint2*)(smem + OFF_B + r * TSTRIDE + c4 * 8)
            = make_uint2(*(uint32_t*)&h0, *(uint32_t*)&h1);
    }
    __syncthreads();                        // the ONLY block barrier (B ready)

    const uint32_t brow = sb + OFF_B + (lane & 15) * TSTRIDE + (lane >> 4) * 16;

    #pragma unroll 1
    for (int mb = 0; mb < 4; mb++) {
        // issue next slice into the other buffer, then complete current group
        if (mb < 3) {
            load_a_warp(aw + ((mb + 1) & 1) * ABUF, mb + 1, wid, lane);
            CP_COMMIT();
            CP_WAIT1();                     // A(mb) done, A(mb+1) in flight
        } else {
            CP_WAIT0();                     // last slice
        }
        __syncwarp();

        float acc[16][4];                   // ni 0..15 (n8 tiles), 4 regs each
        #pragma unroll
        for (int ni = 0; ni < 16; ni++)
            #pragma unroll
            for (int r = 0; r < 4; r++) acc[ni][r] = 0.0f;

        const uint32_t arow = aw + (mb & 1) * ABUF
                            + (lane & 15) * TSTRIDE + (lane >> 4) * 16;
        #pragma unroll
        for (int kk = 0; kk < 8; kk++) {                // 8 k-steps of 16 halves
            uint32_t a[4];
            ldmx4(a, arow + kk * 32);
            #pragma unroll
            for (int t = 0; t < 8; t++) {               // 16 key rows per t
                uint32_t bq[4];
                ldmx4(bq, brow + kk * 32 + t * 16 * TSTRIDE);
                uint32_t b0[2] = {bq[0], bq[2]};        // n8 tile 2t
                uint32_t b1[2] = {bq[1], bq[3]};        // n8 tile 2t+1
                hmma16816(acc[2 * t],     a, b0);
                hmma16816(acc[2 * t + 1], a, b1);
            }
        }

        // ---- epilogue: in-warp base-2 (max, sumexp2); rare-guard self-mask ----
        {
            const int r0l = wid * 16 + (lane >> 2);
            const int q0 = mb * 128 + r0l, q1 = q0 + 8;
            const int msk0 = q0 * KPB + __ldg(&sidx[q0]) - colBase;
            const int msk1 = q1 * KPB + __ldg(&sidx[q1]) - colBase;

            // taken by ~0.8% of warp-instances: overwrite the ONE self logit
            if ((unsigned)msk0 < 128u) {
                #pragma unroll
                for (int ni = 0; ni < 16; ni++) {
                    const int c = ni * 8 + 2 * (lane & 3);
                    if (c     == msk0) acc[ni][0] = NEG_BIG;
                    if (c + 1 == msk0) acc[ni][1] = NEG_BIG;
                }
            }
            if ((unsigned)msk1 < 128u) {
                #pragma unroll
                for (int ni = 0; ni < 16; ni++) {
                    const int c = ni * 8 + 2 * (lane & 3);
                    if (c     == msk1) acc[ni][2] = NEG_BIG;
                    if (c + 1 == msk1) acc[ni][3] = NEG_BIG;
                }
            }

            float m0 = -3.0e38f, m1 = -3.0e38f;
            #pragma unroll
            for (int ni = 0; ni < 16; ni++) {
                m0 = fmaxf(m0, fmaxf(acc[ni][0], acc[ni][1]));
                m1 = fmaxf(m1, fmaxf(acc[ni][2], acc[ni][3]));
            }
            #pragma unroll
            for (int o = 1; o < 4; o <<= 1) {           // row max over the quad
                m0 = fmaxf(m0, __shfl_xor_sync(0xFFFFFFFFu, m0, o));
                m1 = fmaxf(m1, __shfl_xor_sync(0xFFFFFFFFu, m1, o));
            }
            float s0 = 0.0f, s1 = 0.0f;
            #pragma unroll
            for (int ni = 0; ni < 16; ni++) {           // bare EX2, no FFMA
                s0 += exp2f(acc[ni][0] - m0) + exp2f(acc[ni][1] - m0);
                s1 += exp2f(acc[ni][2] - m1) + exp2f(acc[ni][3] - m1);
            }
            #pragma unroll
            for (int o = 1; o < 4; o <<= 1) {           // row sum over the quad
                s0 += __shfl_xor_sync(0xFFFFFFFFu, s0, o);
                s1 += __shfl_xor_sync(0xFFFFFFFFu, s1, o);
            }
            if ((lane & 3) == 0) {
                g_pm[q0 * NTILES + tile] = m0; g_ps[q0 * NTILES + tile] = s0;
                g_pm[q1 * NTILES + tile] = m1; g_ps[q1 * NTILES + tile] = s1;
            }
        }
    }
}

// ---------------------------------------------------------------------------
// Kernel 2 (fused): per query, reduce 2048 base-2 (m,s) partials -> total LSE
// (converted to natural units at the end); own-bag tiles (4b..4b+3) + 261632
// exp2(0)=1 terms -> positive LSE; per-query loss. Last block does the
// fixed-order mean; counter self-resets.
// ---------------------------------------------------------------------------
__global__ void reduce_all(float* __restrict__ out)
{
    __shared__ float sm[256], ss[256];
    __shared__ unsigned int is_last;
    const int b = blockIdx.x, tid = threadIdx.x;

    float m = -3.0e38f, s = 0.0f;
    for (int t = tid; t < NTILES; t += 256) {
        float mo = g_pm[b * NTILES + t], so = g_ps[b * NTILES + t];
        float M = fmaxf(m, mo);
        s = s * exp2f(m - M) + so * exp2f(mo - M);
        m = M;
    }
    sm[tid] = m; ss[tid] = s;
    __syncthreads();
    for (int st = 128; st > 0; st >>= 1) {
        if (tid < st) {
            float m1 = sm[tid], m2 = sm[tid + st];
            float s1 = ss[tid], s2 = ss[tid + st];
            float M = fmaxf(m1, m2);
            sm[tid] = M;
            ss[tid] = s1 * exp2f(m1 - M) + s2 * exp2f(m2 - M);
        }
        __syncthreads();
    }
    if (tid == 0) {
        float lse_tot = LN2 * (sm[0] + log2f(ss[0]));   // back to natural units

        float mp = -3.0e38f, sp = 0.0f;
        #pragma unroll
        for (int p = 0; p < 4; p++) {                  // positive tiles = 4b..4b+3
            float mo = g_pm[b * NTILES + 4 * b + p];
            float so = g_ps[b * NTILES + 4 * b + p];
            float M = fmaxf(mp, mo);
            sp = sp * exp2f(mp - M) + so * exp2f(mo - M);
            mp = M;
        }
        // s_*labels keeps negatives as exp(0)=1 = exp2(0): 261632 of them
        float Mp = fmaxf(mp, 0.0f);
        float Sp = sp * exp2f(mp - Mp) + 261632.0f * exp2f(-Mp);
        float lse_p = LN2 * (Mp + log2f(Sp));

        g_loss[b] = -lse_p + logf(511.0f) + lse_tot;      // num_p = 512 -> 511

        __threadfence();
        is_last = (atomicAdd(&g_done, 1u) == BQ - 1) ? 1u : 0u;
    }
    __syncthreads();
    if (is_last) {                           // final mean, fixed order (deterministic)
        __threadfence();
        sm[tid] = g_loss[tid] + g_loss[tid + 256];
        __syncthreads();
        for (int st = 128; st > 0; st >>= 1) {
            if (tid < st) sm[tid] += sm[tid + st];
            __syncthreads();
        }
        if (tid == 0) {
            out[0] = sm[0] * (1.0f / 512.0f);
            g_done = 0;                      // reset for next graph replay
        }
    }
}

// ---------------------------------------------------------------------------
extern "C" void kernel_launch(void* const* d_in, const int* in_sizes, int n_in,
                              void* d_out, int out_size)
{
    const float* Q    = (const float*)d_in[0];   // [512,128]
    const float* Km   = (const float*)d_in[1];   // [512,512,128]
    const int*   sidx = (const int*)  d_in[2];   // [512]

    cudaFuncSetAttribute(gemm_lse_hmma, cudaFuncAttributeMaxDynamicSharedMemorySize, SMEM_SZ);

    qconv<<<16, 256>>>(Q);
    gemm_lse_hmma<<<NTILES, 256, SMEM_SZ>>>(Km, sidx);
    reduce_all<<<BQ, 256>>>((float*)d_out);
}